// round 6
// baseline (speedup 1.0000x reference)
#include <cuda_runtime.h>
#include <cstdint>

#define D_DIM   128
#define BM      128
#define BN      128
#define TPB     512
#define XSTR    260   // floats/row of duplicated x tile (256 data + 4 pad, 16B-aligned)
#define ESTR    132   // floats/row of e tile (128 data + 4 pad, 16B-aligned)

typedef unsigned long long u64;

__device__ __forceinline__ void fma2(u64 &d, u64 a, u64 b){
    asm("fma.rn.f32x2 %0, %1, %2, %0;" : "+l"(d) : "l"(a), "l"(b));
}
__device__ __forceinline__ void unpack2(u64 v, float &lo, float &hi){
    asm("mov.b64 {%0, %1}, %2;" : "=f"(lo), "=f"(hi) : "l"(v));
}
__device__ __forceinline__ u64 pack2(float lo, float hi){
    u64 r; asm("mov.b64 %0, {%1, %2};" : "=l"(r) : "f"(lo), "f"(hi)); return r;
}

__global__ __launch_bounds__(TPB, 1)
void vq_kernel(const float* __restrict__ x, const float* __restrict__ embed,
               float* __restrict__ outInd, float* __restrict__ outQ, int K)
{
    extern __shared__ float smem[];
    float* xs   = smem;                      // [D_DIM][XSTR] transposed, DUPLICATED x tile
    float* es   = xs + D_DIM * XSTR;         // [D_DIM][ESTR] transposed e tile
    float* xn   = es + D_DIM * ESTR;         // [BM] row norms
    float* en   = xn + BM;                   // [BN] code norms
    int*   sIdx = (int*)(en + BN);           // [BM] winning code per row

    const int t    = threadIdx.x;
    const int lane = t & 31, warp = t >> 5;   // 16 warps
    const int tx   = t & 15, ty   = t >> 4;   // tx: 8-col group, ty: 4-row group (0..31)
    const int m0   = blockIdx.x * BM;

    // ---- load x tile transposed + duplicated (pairs {v,v}) + row norms ----
    for (int r = warp; r < BM; r += 16){
        const float* xr = x + (size_t)(m0 + r) * D_DIM;
        float v0 = xr[lane], v1 = xr[lane+32], v2 = xr[lane+64], v3 = xr[lane+96];
        *(u64*)(xs + (size_t)(lane     )*XSTR + 2*r) = pack2(v0, v0);
        *(u64*)(xs + (size_t)(lane + 32)*XSTR + 2*r) = pack2(v1, v1);
        *(u64*)(xs + (size_t)(lane + 64)*XSTR + 2*r) = pack2(v2, v2);
        *(u64*)(xs + (size_t)(lane + 96)*XSTR + 2*r) = pack2(v3, v3);
        float sq = v0*v0 + v1*v1 + v2*v2 + v3*v3;
        #pragma unroll
        for (int off = 16; off; off >>= 1) sq += __shfl_xor_sync(0xFFFFFFFFu, sq, off);
        if (lane == 0) xn[r] = sq;
    }

    const float NEGINF = __int_as_float(0xff800000);
    float runv[4]; int runi[4];
    #pragma unroll
    for (int i = 0; i < 4; i++){ runv[i] = NEGINF; runi[i] = 0; }

    for (int n0 = 0; n0 < K; n0 += BN){
        __syncthreads();   // previous tile's compute done reading es
        // ---- load e tile transposed + code norms ----
        for (int r = warp; r < BN; r += 16){
            const float* er = embed + (size_t)(n0 + r) * D_DIM;
            float v0 = er[lane], v1 = er[lane+32], v2 = er[lane+64], v3 = er[lane+96];
            es[(size_t)(lane     )*ESTR + r] = v0;
            es[(size_t)(lane + 32)*ESTR + r] = v1;
            es[(size_t)(lane + 64)*ESTR + r] = v2;
            es[(size_t)(lane + 96)*ESTR + r] = v3;
            float sq = v0*v0 + v1*v1 + v2*v2 + v3*v3;
            #pragma unroll
            for (int off = 16; off; off >>= 1) sq += __shfl_xor_sync(0xFFFFFFFFu, sq, off);
            if (lane == 0) en[r] = sq;
        }
        __syncthreads();

        // ---- 128x128 score tile: 4 rows x 8 cols per thread, pure FFMA2 loop ----
        u64 acc[4][4];
        #pragma unroll
        for (int i = 0; i < 4; i++)
            #pragma unroll
            for (int p = 0; p < 4; p++) acc[i][p] = 0ull;

        const float* xa = xs + ty * 8;   // 4 dup-pairs for rows [4ty,4ty+4)
        const float* eb = es + tx * 8;   // 8 cols = 4 native pairs
        #pragma unroll 8
        for (int k = 0; k < D_DIM; k++){
            ulonglong2 aA = *(const ulonglong2*)(xa     + (size_t)k * XSTR);
            ulonglong2 aB = *(const ulonglong2*)(xa + 4 + (size_t)k * XSTR);
            ulonglong2 b0 = *(const ulonglong2*)(eb     + (size_t)k * ESTR);
            ulonglong2 b1 = *(const ulonglong2*)(eb + 4 + (size_t)k * ESTR);
            u64 av[4] = {aA.x, aA.y, aB.x, aB.y};
            #pragma unroll
            for (int i = 0; i < 4; i++){
                fma2(acc[i][0], av[i], b0.x);
                fma2(acc[i][1], av[i], b0.y);
                fma2(acc[i][2], av[i], b1.x);
                fma2(acc[i][3], av[i], b1.y);
            }
        }

        // ---- epilogue: score + per-row argmax (first-occurrence tie-break) ----
        float4 enA = *(const float4*)(en + tx * 8);
        float4 enB = *(const float4*)(en + tx * 8 + 4);
        float env[8] = {enA.x, enA.y, enA.z, enA.w, enB.x, enB.y, enB.z, enB.w};
        #pragma unroll
        for (int i = 0; i < 4; i++){
            int r = ty * 4 + i;
            float xnr = xn[r];
            float bv = NEGINF; int bi = 0;
            #pragma unroll
            for (int p = 0; p < 4; p++){
                float s0, s1; unpack2(acc[i][p], s0, s1);
                float sc0 = (2.0f * s0 - xnr) - env[2*p];
                float sc1 = (2.0f * s1 - xnr) - env[2*p + 1];
                int c0 = n0 + tx * 8 + 2*p, c1 = c0 + 1;
                if (sc0 > bv || (sc0 == bv && c0 < bi)) { bv = sc0; bi = c0; }
                if (sc1 > bv || (sc1 == bv && c1 < bi)) { bv = sc1; bi = c1; }
            }
            // butterfly over the 16 lanes (same ty) sharing this row
            #pragma unroll
            for (int off = 8; off; off >>= 1){
                float ov = __shfl_xor_sync(0xFFFFFFFFu, bv, off);
                int   oi = __shfl_xor_sync(0xFFFFFFFFu, bi, off);
                if (ov > bv || (ov == bv && oi < bi)) { bv = ov; bi = oi; }
            }
            // earlier tiles have smaller indices: strict > keeps first occurrence
            if (bv > runv[i] || (bv == runv[i] && bi < runi[i])) { runv[i] = bv; runi[i] = bi; }
        }
    }

    // ---- write indices (as float) + stash for dequant ----
    if (tx == 0){
        #pragma unroll
        for (int i = 0; i < 4; i++){
            int r = ty * 4 + i;
            sIdx[r] = runi[i];
            outInd[m0 + r] = (float)runi[i];
        }
    }
    __syncthreads();

    // ---- dequantize: quantize[row] = embed[ind[row]] (L2-resident gather) ----
    for (int i = t; i < BM * 32; i += TPB){
        int r = i >> 5, c = i & 31;
        int code = sIdx[r];
        float4 v = *(const float4*)(embed + (size_t)code * D_DIM + c * 4);
        *(float4*)(outQ + (size_t)(m0 + r) * D_DIM + c * 4) = v;
    }
}

extern "C" void kernel_launch(void* const* d_in, const int* in_sizes, int n_in,
                              void* d_out, int out_size)
{
    const float* x     = (const float*)d_in[0];
    const float* embed = (const float*)d_in[1];
    float* out = (float*)d_out;

    int N = in_sizes[0] / D_DIM;   // 131072 rows
    int K = in_sizes[1] / D_DIM;   // 1024 codes

    size_t smem_bytes = (size_t)(D_DIM * XSTR + D_DIM * ESTR + BM + BN) * sizeof(float)
                      + (size_t)BM * sizeof(int);   // ~202,240 B

    cudaFuncSetAttribute(vq_kernel, cudaFuncAttributeMaxDynamicSharedMemorySize,
                         (int)smem_bytes);

    // out layout: [embed_ind (N floats)] then [quantize (N*128 floats)]
    vq_kernel<<<N / BM, TPB, smem_bytes>>>(x, embed, out, out + N, K);
}

// round 7
// speedup vs baseline: 1.4337x; 1.4337x over previous
#include <cuda_runtime.h>
#include <cstdint>

#define D_DIM   128
#define BM      128
#define BN      128
#define TPB     512
#define XSTR    260   // floats/row of duplicated x tile (256 data + 4 pad, 16B-aligned)
#define ESTR    132   // floats/row of e tile (128 data + 4 pad, 16B-aligned)

typedef unsigned long long u64;

__device__ __forceinline__ void fma2(u64 &d, u64 a, u64 b){
    asm("fma.rn.f32x2 %0, %1, %2, %0;" : "+l"(d) : "l"(a), "l"(b));
}
__device__ __forceinline__ void unpack2(u64 v, float &lo, float &hi){
    asm("mov.b64 {%0, %1}, %2;" : "=f"(lo), "=f"(hi) : "l"(v));
}
__device__ __forceinline__ u64 pack2(float lo, float hi){
    u64 r; asm("mov.b64 %0, {%1, %2};" : "=l"(r) : "f"(lo), "f"(hi)); return r;
}

__global__ __launch_bounds__(TPB, 1)
void vq_kernel(const float* __restrict__ x, const float* __restrict__ embed,
               float* __restrict__ outInd, float* __restrict__ outQ, int K)
{
    extern __shared__ float smem[];
    float* xs   = smem;                      // [D_DIM][XSTR] transposed, DUPLICATED x tile
    float* es   = xs + D_DIM * XSTR;         // [D_DIM][ESTR] transposed e tile
    float* xn   = es + D_DIM * ESTR;         // [BM] row norms
    float* en   = xn + BM;                   // [BN] code norms
    int*   sIdx = (int*)(en + BN);           // [BM] winning code per row

    const int t    = threadIdx.x;
    const int lane = t & 31, warp = t >> 5;   // 16 warps
    const int tx   = t & 15, ty   = t >> 4;   // tx: col group, ty: 4-row group (0..31)
    const int m0   = blockIdx.x * BM;

    // ---- load x tile transposed + duplicated (pairs {v,v}) + row norms ----
    for (int r = warp; r < BM; r += 16){
        const float* xr = x + (size_t)(m0 + r) * D_DIM;
        float v0 = xr[lane], v1 = xr[lane+32], v2 = xr[lane+64], v3 = xr[lane+96];
        *(u64*)(xs + (size_t)(lane     )*XSTR + 2*r) = pack2(v0, v0);
        *(u64*)(xs + (size_t)(lane + 32)*XSTR + 2*r) = pack2(v1, v1);
        *(u64*)(xs + (size_t)(lane + 64)*XSTR + 2*r) = pack2(v2, v2);
        *(u64*)(xs + (size_t)(lane + 96)*XSTR + 2*r) = pack2(v3, v3);
        float sq = v0*v0 + v1*v1 + v2*v2 + v3*v3;
        #pragma unroll
        for (int off = 16; off; off >>= 1) sq += __shfl_xor_sync(0xFFFFFFFFu, sq, off);
        if (lane == 0) xn[r] = sq;
    }

    const float NEGINF = __int_as_float(0xff800000);
    float runv[4]; int runi[4];
    #pragma unroll
    for (int i = 0; i < 4; i++){ runv[i] = NEGINF; runi[i] = 0; }

    for (int n0 = 0; n0 < K; n0 += BN){
        __syncthreads();   // previous tile's compute done reading es
        // ---- load e tile transposed + code norms ----
        for (int r = warp; r < BN; r += 16){
            const float* er = embed + (size_t)(n0 + r) * D_DIM;
            float v0 = er[lane], v1 = er[lane+32], v2 = er[lane+64], v3 = er[lane+96];
            es[(size_t)(lane     )*ESTR + r] = v0;
            es[(size_t)(lane + 32)*ESTR + r] = v1;
            es[(size_t)(lane + 64)*ESTR + r] = v2;
            es[(size_t)(lane + 96)*ESTR + r] = v3;
            float sq = v0*v0 + v1*v1 + v2*v2 + v3*v3;
            #pragma unroll
            for (int off = 16; off; off >>= 1) sq += __shfl_xor_sync(0xFFFFFFFFu, sq, off);
            if (lane == 0) en[r] = sq;
        }
        __syncthreads();

        // ---- 128x128 score tile: 4 rows x 8 cols/thread, conflict-free LDS ----
        // cols: {tx*4 .. tx*4+3} and {64+tx*4 .. 64+tx*4+3}  (16B stride — no conflicts)
        u64 acc[4][4];
        #pragma unroll
        for (int i = 0; i < 4; i++)
            #pragma unroll
            for (int p = 0; p < 4; p++) acc[i][p] = 0ull;

        const float* xa = xs + ty * 8;    // 4 dup-pairs for rows [4ty,4ty+4)
        const float* eb = es + tx * 4;    // first 4-col group; second at +64
        #pragma unroll 8
        for (int k = 0; k < D_DIM; k++){
            ulonglong2 aA = *(const ulonglong2*)(xa     + (size_t)k * XSTR);
            ulonglong2 aB = *(const ulonglong2*)(xa + 4 + (size_t)k * XSTR);
            ulonglong2 b0 = *(const ulonglong2*)(eb      + (size_t)k * ESTR);
            ulonglong2 b1 = *(const ulonglong2*)(eb + 64 + (size_t)k * ESTR);
            u64 av[4] = {aA.x, aA.y, aB.x, aB.y};
            #pragma unroll
            for (int i = 0; i < 4; i++){
                fma2(acc[i][0], av[i], b0.x);
                fma2(acc[i][1], av[i], b0.y);
                fma2(acc[i][2], av[i], b1.x);
                fma2(acc[i][3], av[i], b1.y);
            }
        }

        // ---- epilogue: score + per-row argmax (first-occurrence tie-break) ----
        float4 enA = *(const float4*)(en + tx * 4);
        float4 enB = *(const float4*)(en + 64 + tx * 4);
        float env[8] = {enA.x, enA.y, enA.z, enA.w, enB.x, enB.y, enB.z, enB.w};
        #pragma unroll
        for (int i = 0; i < 4; i++){
            int r = ty * 4 + i;
            float xnr = xn[r];
            float bv = NEGINF; int bi = 0;
            #pragma unroll
            for (int p = 0; p < 4; p++){
                float s0, s1; unpack2(acc[i][p], s0, s1);
                float sc0 = (2.0f * s0 - xnr) - env[2*p];
                float sc1 = (2.0f * s1 - xnr) - env[2*p + 1];
                int cbase = (p < 2) ? (tx*4 + 2*p) : (64 + tx*4 + 2*(p - 2));
                int c0 = n0 + cbase, c1 = c0 + 1;
                if (sc0 > bv || (sc0 == bv && c0 < bi)) { bv = sc0; bi = c0; }
                if (sc1 > bv || (sc1 == bv && c1 < bi)) { bv = sc1; bi = c1; }
            }
            // butterfly over the 16 lanes (same ty) sharing this row
            #pragma unroll
            for (int off = 8; off; off >>= 1){
                float ov = __shfl_xor_sync(0xFFFFFFFFu, bv, off);
                int   oi = __shfl_xor_sync(0xFFFFFFFFu, bi, off);
                if (ov > bv || (ov == bv && oi < bi)) { bv = ov; bi = oi; }
            }
            // earlier tiles have smaller indices: strict > keeps first occurrence
            if (bv > runv[i] || (bv == runv[i] && bi < runi[i])) { runv[i] = bv; runi[i] = bi; }
        }
    }

    // ---- write indices (as float) + stash for dequant ----
    if (tx == 0){
        #pragma unroll
        for (int i = 0; i < 4; i++){
            int r = ty * 4 + i;
            sIdx[r] = runi[i];
            outInd[m0 + r] = (float)runi[i];
        }
    }
    __syncthreads();

    // ---- dequantize: quantize[row] = embed[ind[row]] (L2-resident gather) ----
    for (int i = t; i < BM * 32; i += TPB){
        int r = i >> 5, c = i & 31;
        int code = sIdx[r];
        float4 v = *(const float4*)(embed + (size_t)code * D_DIM + c * 4);
        *(float4*)(outQ + (size_t)(m0 + r) * D_DIM + c * 4) = v;
    }
}

extern "C" void kernel_launch(void* const* d_in, const int* in_sizes, int n_in,
                              void* d_out, int out_size)
{
    const float* x     = (const float*)d_in[0];
    const float* embed = (const float*)d_in[1];
    float* out = (float*)d_out;

    int N = in_sizes[0] / D_DIM;   // 131072 rows
    int K = in_sizes[1] / D_DIM;   // 1024 codes

    size_t smem_bytes = (size_t)(D_DIM * XSTR + D_DIM * ESTR + BM + BN) * sizeof(float)
                      + (size_t)BM * sizeof(int);   // ~202,240 B

    cudaFuncSetAttribute(vq_kernel, cudaFuncAttributeMaxDynamicSharedMemorySize,
                         (int)smem_bytes);

    // out layout: [embed_ind (N floats)] then [quantize (N*128 floats)]
    vq_kernel<<<N / BM, TPB, smem_bytes>>>(x, embed, out, out + N, K);
}

// round 8
// speedup vs baseline: 1.5241x; 1.0631x over previous
#include <cuda_runtime.h>
#include <cstdint>

#define D_DIM   128
#define BM      128
#define BN      256
#define TPB     256
#define XSTR    132   // floats/row of x tile (128 data + 4 pad, 16B-aligned)
#define ESTR    260   // floats/row of e tile (256 data + 4 pad, 16B-aligned)

typedef unsigned long long u64;

__device__ __forceinline__ void fma2(u64 &d, u64 a, u64 b){
    asm("fma.rn.f32x2 %0, %1, %2, %0;" : "+l"(d) : "l"(a), "l"(b));
}
__device__ __forceinline__ void unpack2(u64 v, float &lo, float &hi){
    asm("mov.b64 {%0, %1}, %2;" : "=f"(lo), "=f"(hi) : "l"(v));
}
__device__ __forceinline__ u64 packdup(float a){
    u64 r; asm("mov.b64 %0, {%1, %1};" : "=l"(r) : "f"(a)); return r;
}

__global__ __launch_bounds__(TPB, 1)
void vq_kernel(const float* __restrict__ x, const float* __restrict__ embed,
               float* __restrict__ outInd, float* __restrict__ outQ, int K)
{
    extern __shared__ float smem[];
    float* xs   = smem;                      // [D_DIM][XSTR] transposed x tile
    float* es   = xs + D_DIM * XSTR;         // [D_DIM][ESTR] transposed e tile (256 cols)
    float* xn   = es + D_DIM * ESTR;         // [BM] row norms
    float* en   = xn + BM;                   // [BN] code norms
    int*   sIdx = (int*)(en + BN);           // [BM] winning code per row

    const int t    = threadIdx.x;
    const int lane = t & 31, warp = t >> 5;   // 8 warps
    const int tx   = t & 15, ty   = t >> 4;   // tx: col group (16 cols), ty: 8-row group
    const int m0   = blockIdx.x * BM;

    // ---- load x tile transposed + row norms ----
    for (int r = warp; r < BM; r += 8){
        const float* xr = x + (size_t)(m0 + r) * D_DIM;
        float v0 = xr[lane], v1 = xr[lane+32], v2 = xr[lane+64], v3 = xr[lane+96];
        xs[(size_t)(lane     )*XSTR + r] = v0;
        xs[(size_t)(lane + 32)*XSTR + r] = v1;
        xs[(size_t)(lane + 64)*XSTR + r] = v2;
        xs[(size_t)(lane + 96)*XSTR + r] = v3;
        float sq = v0*v0 + v1*v1 + v2*v2 + v3*v3;
        #pragma unroll
        for (int off = 16; off; off >>= 1) sq += __shfl_xor_sync(0xFFFFFFFFu, sq, off);
        if (lane == 0) xn[r] = sq;
    }

    const float NEGINF = __int_as_float(0xff800000);
    float runv[8]; int runi[8];
    #pragma unroll
    for (int i = 0; i < 8; i++){ runv[i] = NEGINF; runi[i] = 0; }

    for (int n0 = 0; n0 < K; n0 += BN){
        __syncthreads();   // previous tile's compute done reading es
        // ---- load e tile (256 codes) transposed + code norms ----
        for (int r = warp; r < BN; r += 8){
            const float* er = embed + (size_t)(n0 + r) * D_DIM;
            float v0 = er[lane], v1 = er[lane+32], v2 = er[lane+64], v3 = er[lane+96];
            es[(size_t)(lane     )*ESTR + r] = v0;
            es[(size_t)(lane + 32)*ESTR + r] = v1;
            es[(size_t)(lane + 64)*ESTR + r] = v2;
            es[(size_t)(lane + 96)*ESTR + r] = v3;
            float sq = v0*v0 + v1*v1 + v2*v2 + v3*v3;
            #pragma unroll
            for (int off = 16; off; off >>= 1) sq += __shfl_xor_sync(0xFFFFFFFFu, sq, off);
            if (lane == 0) en[r] = sq;
        }
        __syncthreads();

        // ---- 128x256 score tile: 8 rows x 16 cols per thread ----
        // cols in 4 conflict-free groups: g*64 + tx*4 .. +3  (16B lane stride)
        u64 acc[8][8];
        #pragma unroll
        for (int i = 0; i < 8; i++)
            #pragma unroll
            for (int j = 0; j < 8; j++) acc[i][j] = 0ull;

        const float* xa = xs + ty * 8;    // rows [8ty, 8ty+8)
        const float* eb = es + tx * 4;    // col groups at +0, +64, +128, +192
        #pragma unroll 4
        for (int k = 0; k < D_DIM; k++){
            float4 ar0 = *(const float4*)(xa     + (size_t)k * XSTR);
            float4 ar1 = *(const float4*)(xa + 4 + (size_t)k * XSTR);
            ulonglong2 b0 = *(const ulonglong2*)(eb       + (size_t)k * ESTR);
            ulonglong2 b1 = *(const ulonglong2*)(eb +  64 + (size_t)k * ESTR);
            ulonglong2 b2 = *(const ulonglong2*)(eb + 128 + (size_t)k * ESTR);
            ulonglong2 b3 = *(const ulonglong2*)(eb + 192 + (size_t)k * ESTR);
            u64 a[8] = { packdup(ar0.x), packdup(ar0.y), packdup(ar0.z), packdup(ar0.w),
                         packdup(ar1.x), packdup(ar1.y), packdup(ar1.z), packdup(ar1.w) };
            #pragma unroll
            for (int i = 0; i < 8; i++){
                fma2(acc[i][0], a[i], b0.x);
                fma2(acc[i][1], a[i], b0.y);
                fma2(acc[i][2], a[i], b1.x);
                fma2(acc[i][3], a[i], b1.y);
                fma2(acc[i][4], a[i], b2.x);
                fma2(acc[i][5], a[i], b2.y);
                fma2(acc[i][6], a[i], b3.x);
                fma2(acc[i][7], a[i], b3.y);
            }
        }

        // ---- epilogue: score + per-row argmax (first-occurrence tie-break) ----
        float env[8][2];
        #pragma unroll
        for (int g = 0; g < 4; g++){
            float4 e4 = *(const float4*)(en + g * 64 + tx * 4);
            env[2*g  ][0] = e4.x; env[2*g  ][1] = e4.y;
            env[2*g+1][0] = e4.z; env[2*g+1][1] = e4.w;
        }
        #pragma unroll
        for (int i = 0; i < 8; i++){
            int r = ty * 8 + i;
            float xnr = xn[r];
            float bv = NEGINF; int bi = 0;
            #pragma unroll
            for (int j = 0; j < 8; j++){
                float s0, s1; unpack2(acc[i][j], s0, s1);
                float sc0 = (2.0f * s0 - xnr) - env[j][0];
                float sc1 = (2.0f * s1 - xnr) - env[j][1];
                int c0 = n0 + (j >> 1) * 64 + tx * 4 + (j & 1) * 2;
                int c1 = c0 + 1;
                if (sc0 > bv || (sc0 == bv && c0 < bi)) { bv = sc0; bi = c0; }
                if (sc1 > bv || (sc1 == bv && c1 < bi)) { bv = sc1; bi = c1; }
            }
            // butterfly over the 16 lanes (same ty) sharing this row
            #pragma unroll
            for (int off = 8; off; off >>= 1){
                float ov = __shfl_xor_sync(0xFFFFFFFFu, bv, off);
                int   oi = __shfl_xor_sync(0xFFFFFFFFu, bi, off);
                if (ov > bv || (ov == bv && oi < bi)) { bv = ov; bi = oi; }
            }
            // earlier tiles have smaller indices: strict > keeps first occurrence
            if (bv > runv[i] || (bv == runv[i] && bi < runi[i])) { runv[i] = bv; runi[i] = bi; }
        }
    }

    // ---- write indices (as float) + stash for dequant ----
    if (tx == 0){
        #pragma unroll
        for (int i = 0; i < 8; i++){
            int r = ty * 8 + i;
            sIdx[r] = runi[i];
            outInd[m0 + r] = (float)runi[i];
        }
    }
    __syncthreads();

    // ---- dequantize: quantize[row] = embed[ind[row]] (L2-resident gather) ----
    for (int i = t; i < BM * 32; i += TPB){
        int r = i >> 5, c = i & 31;
        int code = sIdx[r];
        float4 v = *(const float4*)(embed + (size_t)code * D_DIM + c * 4);
        *(float4*)(outQ + (size_t)(m0 + r) * D_DIM + c * 4) = v;
    }
}

extern "C" void kernel_launch(void* const* d_in, const int* in_sizes, int n_in,
                              void* d_out, int out_size)
{
    const float* x     = (const float*)d_in[0];
    const float* embed = (const float*)d_in[1];
    float* out = (float*)d_out;

    int N = in_sizes[0] / D_DIM;   // 131072 rows
    int K = in_sizes[1] / D_DIM;   // 1024 codes

    size_t smem_bytes = (size_t)(D_DIM * XSTR + D_DIM * ESTR + BM + BN) * sizeof(float)
                      + (size_t)BM * sizeof(int);   // 202,752 B

    cudaFuncSetAttribute(vq_kernel, cudaFuncAttributeMaxDynamicSharedMemorySize,
                         (int)smem_bytes);

    // out layout: [embed_ind (N floats)] then [quantize (N*128 floats)]
    vq_kernel<<<N / BM, TPB, smem_bytes>>>(x, embed, out, out + N, K);
}